// round 6
// baseline (speedup 1.0000x reference)
#include <cuda_runtime.h>
#include <math.h>
#include <stdint.h>

#define BB    32
#define NFEAT 80
#define TXD   512
#define TYD   2048
#define NEGV  (-1e9f)
#define LOG2PI_F 1.8378770664093453f
#define NZCTA 116            // zero-fill CTAs inside k_dp launch (148 - 32)

// ---------------- static device scratch ------------------------------------
// g_S column storage is PERMUTED: within each [b][j] column of 512 floats,
// quad p (rows 4p..4p+3) is stored at slot s(p) = (p&3)*32 + (p>>2).
// => DP thread t reads slots {g*32+t : g=0..3} (lane-contiguous LDG.128) and
//    receives rows 16t..16t+15 (contiguous ownership, 1 shuffle per step).
__device__ float g_S[(size_t)BB * TYD * TXD];
__device__ float g_mm[BB * TXD];
__device__ int   g_sout[BB][TXD + 1];              // enter times s_i (e_i = s_{i+1})
__device__ unsigned short g_idx[BB][TYD];
__device__ float g_dur_part[BB];
__device__ float g_prior_part[BB * 8];

// ---------------- f32x2 packed-FMA helpers ---------------------------------
__device__ __forceinline__ unsigned long long pk2(float x, float y) {
    unsigned long long r; asm("mov.b64 %0, {%1, %2};" : "=l"(r) : "f"(x), "f"(y)); return r;
}
__device__ __forceinline__ unsigned long long fma2(unsigned long long a, unsigned long long b,
                                                   unsigned long long c) {
    unsigned long long d; asm("fma.rn.f32x2 %0, %1, %2, %3;" : "=l"(d) : "l"(a), "l"(b), "l"(c));
    return d;
}
__device__ __forceinline__ unsigned long long add2(unsigned long long a, unsigned long long b) {
    unsigned long long d; asm("add.rn.f32x2 %0, %1, %2;" : "=l"(d) : "l"(a), "l"(b));
    return d;
}

// ---------------- K0: mm[b,i] = -0.5 * sum_c mu^2 --------------------------
__global__ void k_mm(const float* __restrict__ mu) {
    int b = blockIdx.x, i = threadIdx.x;
    const float* p = mu + (size_t)b * NFEAT * TXD + i;
    float s = 0.f;
#pragma unroll
    for (int c = 0; c < NFEAT; c++) { float v = p[(size_t)c * TXD]; s += v * v; }
    g_mm[b * TXD + i] = -0.5f * s;
}

// ---------------- K1: batched GEMM via packed f32x2 FMA ---------------------
#define GEMM_SMEM (NFEAT * 256 * 4 + NFEAT * 64 * 4)   // 102400 bytes
__global__ __launch_bounds__(256) void k_gemm(const float* __restrict__ mu,
                                              const float* __restrict__ y,
                                              const int* __restrict__ yl) {
    int b = blockIdx.z;
    int jj0 = blockIdx.y * 64;
    if (jj0 >= yl[b]) return;                       // columns beyond ylen never read

    extern __shared__ float sm[];
    float* mus = sm;                  // [80][256]
    float* ys  = sm + NFEAT * 256;    // [80][64]
    int ii0 = blockIdx.x * 256;
    int tid = threadIdx.x;

    const float* mub = mu + (size_t)b * NFEAT * TXD + ii0;
    for (int idx = tid; idx < NFEAT * 256; idx += 256) {
        int c = idx >> 8, i = idx & 255;
        mus[idx] = mub[(size_t)c * TXD + i];
    }
    const float* yb = y + (size_t)b * NFEAT * TYD + jj0;
    for (int idx = tid; idx < NFEAT * 64; idx += 256) {
        int c = idx >> 6, jj = idx & 63;
        ys[idx] = yb[(size_t)c * TYD + jj];
    }
    __syncthreads();

    int tx = tid & 31, ty = tid >> 5;
    unsigned long long acc[8][4];
#pragma unroll
    for (int r = 0; r < 8; r++)
#pragma unroll
        for (int k = 0; k < 4; k++) acc[r][k] = 0ULL;

#pragma unroll 4
    for (int c = 0; c < NFEAT; c++) {
        const float4 a0 = *(const float4*)(ys + c * 64 + (ty << 3));
        const float4 a1 = *(const float4*)(ys + c * 64 + (ty << 3) + 4);
        const ulonglong2 m01 = *(const ulonglong2*)(mus + (c << 8) + (tx << 3));
        const ulonglong2 m23 = *(const ulonglong2*)(mus + (c << 8) + (tx << 3) + 4);
        unsigned long long mv[4] = {m01.x, m01.y, m23.x, m23.y};
        float av[8] = {a0.x, a0.y, a0.z, a0.w, a1.x, a1.y, a1.z, a1.w};
#pragma unroll
        for (int r = 0; r < 8; r++) {
            unsigned long long ar = pk2(av[r], av[r]);
#pragma unroll
            for (int k = 0; k < 4; k++) acc[r][k] = fma2(ar, mv[k], acc[r][k]);
        }
    }

    const ulonglong2 mmA = *(const ulonglong2*)(g_mm + b * TXD + ii0 + (tx << 3));
    const ulonglong2 mmB = *(const ulonglong2*)(g_mm + b * TXD + ii0 + (tx << 3) + 4);
    unsigned long long mmv[4] = {mmA.x, mmA.y, mmB.x, mmB.y};

    // sigma-permuted store slots for this thread's two quads
    int p0 = (ii0 >> 2) + 2 * tx;
    int p1 = p0 + 1;
    int sl0 = ((p0 & 3) << 5) + (p0 >> 2);
    int sl1 = ((p1 & 3) << 5) + (p1 >> 2);

#pragma unroll
    for (int r = 0; r < 8; r++) {
        int j = jj0 + (ty << 3) + r;
        float* base = g_S + ((size_t)b * TYD + j) * TXD;
        ulonglong2 o0, o1;
        o0.x = add2(acc[r][0], mmv[0]); o0.y = add2(acc[r][1], mmv[1]);
        o1.x = add2(acc[r][2], mmv[2]); o1.y = add2(acc[r][3], mmv[3]);
        *(ulonglong2*)(base + sl0 * 4) = o0;
        *(ulonglong2*)(base + sl1 * 4) = o1;
    }
}

// ---------------- K2: register-ring Viterbi DP + fused attn zero-fill -------
// CTAs 0..31: 1 warp each, thread t owns contiguous rows [16t, 16t+16).
// Depth-8 register ring of columns loaded via lane-contiguous LDG.128 from the
// sigma-permuted g_S. One shfl_up per step. Direction bits per thread (u16).
// CTAs 32..147: zero-fill the 128MB attn output region concurrently.
#define DP_SMEM (TYD * 32 * 2)     // 128KB dirs

__global__ __launch_bounds__(32) void k_dp(const int* __restrict__ xl,
                                           const int* __restrict__ yl,
                                           float* __restrict__ out) {
    int cta = blockIdx.x;
    int t = threadIdx.x;

    if (cta >= BB) {
        // ---------- zero-fill attn [2, 2+BB*TXD*TYD) ----------
        const size_t NTOT = (size_t)BB * TXD * TYD;       // 33554432
        const size_t n4 = (NTOT - 2) >> 2;                // float4 count from out+4
        float4 z4 = make_float4(0.f, 0.f, 0.f, 0.f);
        float4* p4 = (float4*)(out + 4);
        for (size_t q = (size_t)(cta - BB) * 32 + t; q < n4; q += (size_t)NZCTA * 32)
            p4[q] = z4;
        if (cta == BB && t == 0) {
            out[2] = 0.f; out[3] = 0.f;
            out[NTOT] = 0.f; out[NTOT + 1] = 0.f;
        }
        return;
    }

    extern __shared__ unsigned short dirs[];              // [TYD][32]
    int b = cta;
    int xlen = xl[b], ylen = yl[b];
    const float* colbase = g_S + (size_t)b * TYD * TXD;

    float buf[8][16];
    // prologue: columns 0..7
#pragma unroll
    for (int s2 = 0; s2 < 8; s2++) {
        const float4* cp = (const float4*)(colbase + s2 * TXD);
#pragma unroll
        for (int g = 0; g < 4; g++) {
            float4 f = cp[g * 32 + t];
            buf[s2][4 * g + 0] = f.x; buf[s2][4 * g + 1] = f.y;
            buf[s2][4 * g + 2] = f.z; buf[s2][4 * g + 3] = f.w;
        }
    }

    float v[16];
#pragma unroll
    for (int m = 0; m < 16; m++) v[m] = NEGV;
    if (t == 0) v[0] = buf[0][0];             // lp(0,0): only row 0 alive at j=0

    // slot 0 consumed by init; refill with column 8 (ylen >= 1024 always)
    {
        const float4* cp = (const float4*)(colbase + (size_t)8 * TXD);
#pragma unroll
        for (int g = 0; g < 4; g++) {
            float4 f = cp[g * 32 + t];
            buf[0][4 * g + 0] = f.x; buf[0][4 * g + 1] = f.y;
            buf[0][4 * g + 2] = f.z; buf[0][4 * g + 3] = f.w;
        }
    }

    for (int jb = 0; jb < ylen; jb += 8) {
#pragma unroll
        for (int s2 = 0; s2 < 8; s2++) {
            int j = jb + s2;
            if (j == 0) continue;
            if (j >= ylen) break;

            float sh = __shfl_up_sync(0xffffffffu, v[15], 1);
            unsigned sg = 0;
#pragma unroll
            for (int m = 15; m >= 1; m--) {
                float vs = v[m - 1];
                float d_ = vs - v[m];
                sg |= (__float_as_uint(d_) >> 31) << m;   // sign=1 -> NOT diag
                v[m] = buf[s2][m] + fmaxf(v[m], vs);
            }
            float vs0 = (t == 0) ? NEGV : sh;
            float d0 = vs0 - v[0];
            sg |= (__float_as_uint(d0) >> 31);
            v[0] = buf[s2][0] + fmaxf(v[0], vs0);
            dirs[j * 32 + t] = (unsigned short)(~sg);     // bit=1 -> diag (vs>=v)

            int jn = j + 8;
            if (jn < ylen) {
                const float4* cp = (const float4*)(colbase + (size_t)jn * TXD);
#pragma unroll
                for (int g = 0; g < 4; g++) {
                    float4 f = cp[g * 32 + t];
                    buf[s2][4 * g + 0] = f.x; buf[s2][4 * g + 1] = f.y;
                    buf[s2][4 * g + 2] = f.z; buf[s2][4 * g + 3] = f.w;
                }
            }
        }
    }

    // default (empty) intervals
    for (int i2 = t; i2 <= TXD; i2 += 32) g_sout[b][i2] = ylen;
    __syncwarp();

    // backtrack: pipelined 4 levels per anchor, speculative candidate loads
    if (t == 0) {
#define TIXn(ii) ((ii) >> 4)
#define DBITn(w, ii) (((w) >> ((ii) & 15)) & 1)
        int i = xlen - 1;
        int j = ylen - 1;
        while (j >= 4) {
            int q = j * 32;
            unsigned w0  = dirs[q       + TIXn(i)];
            unsigned w1a = dirs[q - 32  + TIXn(i)],     w1b = dirs[q - 32 + TIXn(i - 1)];
            unsigned w2a = dirs[q - 64  + TIXn(i)],     w2b = dirs[q - 64 + TIXn(i - 1)];
            unsigned w2c = dirs[q - 64  + TIXn(i - 2)];
            unsigned w3a = dirs[q - 96  + TIXn(i)],     w3b = dirs[q - 96 + TIXn(i - 1)];
            unsigned w3c = dirs[q - 96  + TIXn(i - 2)], w3d = dirs[q - 96 + TIXn(i - 3)];
            int s = 0;
            int d = (i > 0) ? DBITn(w0, i) : 0;
            if (d) { g_sout[b][i] = j; i--; s = 1; }
            unsigned w = s ? w1b : w1a;
            d = (i > 0) ? DBITn(w, i) : 0;
            if (d) { g_sout[b][i] = j - 1; i--; s++; }
            w = (s == 0) ? w2a : (s == 1) ? w2b : w2c;
            d = (i > 0) ? DBITn(w, i) : 0;
            if (d) { g_sout[b][i] = j - 2; i--; s++; }
            w = (s == 0) ? w3a : (s == 1) ? w3b : (s == 2) ? w3c : w3d;
            d = (i > 0) ? DBITn(w, i) : 0;
            if (d) { g_sout[b][i] = j - 3; i--; }
            j -= 4;
        }
        for (; j >= 1; j--) {
            unsigned w = dirs[j * 32 + TIXn(i)];
            int d = (i > 0) ? DBITn(w, i) : 0;
            if (d) { g_sout[b][i] = j; i--; }
        }
        g_sout[b][0] = 0;
    }
}

// ---------------- K3: ones + idx map + duration loss (fused) ----------------
__global__ void k_ones(float* __restrict__ out, const float* __restrict__ logw,
                       const int* __restrict__ xl) {
    int b = blockIdx.x, i = threadIdx.x;                 // 512 threads
    int xlen = xl[b];
    int s = g_sout[b][i];
    int e = g_sout[b][i + 1];
    float* row = out + 2 + ((size_t)(b * TXD + i)) * TYD;
    for (int tt = s; tt < e; tt++) {                     // empty when i >= xlen
        row[tt] = 1.f;
        g_idx[b][tt] = (unsigned short)i;
    }
    float val = 0.f;
    if (i < xlen) {
        float lw = logw[b * TXD + i];
        float diff = lw - logf(1e-8f + (float)(e - s));
        val = diff * diff;
    }
    __shared__ float red[512];
    red[i] = val;
    __syncthreads();
    for (int off = 256; off > 0; off >>= 1) {
        if (i < off) red[i] += red[i + off];
        __syncthreads();
    }
    if (i == 0) g_dur_part[b] = red[0];
}

// ---------------- K4: prior loss partials -----------------------------------
__global__ void k_prior(const float* __restrict__ mu, const float* __restrict__ y,
                        const int* __restrict__ yl) {
    int b = blockIdx.y;
    int t = blockIdx.x * 256 + threadIdx.x;
    float acc = 0.f;
    if (t < yl[b]) {
        int k = g_idx[b][t];
        const float* yp = y + (size_t)b * NFEAT * TYD + t;
        const float* mp = mu + (size_t)b * NFEAT * TXD + k;
#pragma unroll 8
        for (int c = 0; c < NFEAT; c++) {
            float d = yp[(size_t)c * TYD] - mp[(size_t)c * TXD];
            acc += d * d;
        }
    }
    __shared__ float red[256];
    red[threadIdx.x] = acc;
    __syncthreads();
    for (int off = 128; off > 0; off >>= 1) {
        if (threadIdx.x < off) red[threadIdx.x] += red[threadIdx.x + off];
        __syncthreads();
    }
    if (threadIdx.x == 0) g_prior_part[b * 8 + blockIdx.x] = red[0];
}

// ---------------- K5: finalize scalars --------------------------------------
__global__ void k_final(float* __restrict__ out, const int* __restrict__ xl,
                        const int* __restrict__ yl) {
    if (threadIdx.x != 0) return;
    float ds = 0.f;
    for (int b = 0; b < BB; b++) ds += g_dur_part[b];
    float ps = 0.f;
    for (int q = 0; q < BB * 8; q++) ps += g_prior_part[q];
    int sx = 0, sy = 0;
    for (int b = 0; b < BB; b++) { sx += xl[b]; sy += yl[b]; }
    out[0] = ds / (float)sx;
    out[1] = 0.5f * ps / ((float)sy * (float)NFEAT) + 0.5f * LOG2PI_F;
}

// ---------------- launch ----------------------------------------------------
extern "C" void kernel_launch(void* const* d_in, const int* in_sizes, int n_in,
                              void* d_out, int out_size) {
    const float* mu   = (const float*)d_in[0];
    const float* logw = (const float*)d_in[1];
    const float* y    = (const float*)d_in[2];
    const int*   xl   = (const int*)d_in[3];
    const int*   yl   = (const int*)d_in[4];
    float* out = (float*)d_out;

    cudaFuncSetAttribute(k_gemm, cudaFuncAttributeMaxDynamicSharedMemorySize, GEMM_SMEM);
    cudaFuncSetAttribute(k_dp,   cudaFuncAttributeMaxDynamicSharedMemorySize, DP_SMEM);

    k_mm<<<BB, TXD>>>(mu);
    k_gemm<<<dim3(TXD / 256, TYD / 64, BB), 256, GEMM_SMEM>>>(mu, y, yl);
    k_dp<<<BB + NZCTA, 32, DP_SMEM>>>(xl, yl, out);
    k_ones<<<BB, TXD>>>(out, logw, xl);
    k_prior<<<dim3(TYD / 256, BB), 256>>>(mu, y, yl);
    k_final<<<1, 32>>>(out, xl, yl);
}

// round 7
// speedup vs baseline: 1.1707x; 1.1707x over previous
#include <cuda_runtime.h>
#include <math.h>
#include <stdint.h>

#define BB    32
#define NFEAT 80
#define TXD   512
#define TYD   2048
#define NEGV  (-1e9f)
#define LOG2PI_F 1.8378770664093453f

// ---------------- static device scratch ------------------------------------
// g_S column storage is PERMUTED: within each [b][j] column of 512 floats,
// quad p (rows 4p..4p+3) is stored at slot s(p) = (p&3)*32 + (p>>2).
// => DP thread t reads slots {g*32+t : g=0..3} (lane-contiguous LDG.128) and
//    receives rows 16t..16t+15 (contiguous ownership, 1 shuffle per step).
__device__ float g_S[(size_t)BB * TYD * TXD];
__device__ float g_mm[BB * TXD];
__device__ int   g_sout[BB][TXD + 1];              // enter times s_i (e_i = s_{i+1})
__device__ unsigned short g_idx[BB][TYD];
__device__ float g_dur_part[BB];
__device__ float g_prior_part[BB * 8];

// ---------------- f32x2 packed-FMA helpers ---------------------------------
__device__ __forceinline__ unsigned long long pk2(float x, float y) {
    unsigned long long r; asm("mov.b64 %0, {%1, %2};" : "=l"(r) : "f"(x), "f"(y)); return r;
}
__device__ __forceinline__ unsigned long long fma2(unsigned long long a, unsigned long long b,
                                                   unsigned long long c) {
    unsigned long long d; asm("fma.rn.f32x2 %0, %1, %2, %3;" : "=l"(d) : "l"(a), "l"(b), "l"(c));
    return d;
}
__device__ __forceinline__ unsigned long long add2(unsigned long long a, unsigned long long b) {
    unsigned long long d; asm("add.rn.f32x2 %0, %1, %2;" : "=l"(d) : "l"(a), "l"(b));
    return d;
}

// ---------------- K0: mm[b,i] = -0.5 * sum_c mu^2 --------------------------
__global__ void k_mm(const float* __restrict__ mu) {
    int b = blockIdx.x, i = threadIdx.x;
    const float* p = mu + (size_t)b * NFEAT * TXD + i;
    float s = 0.f;
#pragma unroll
    for (int c = 0; c < NFEAT; c++) { float v = p[(size_t)c * TXD]; s += v * v; }
    g_mm[b * TXD + i] = -0.5f * s;
}

// ---------------- K1: batched GEMM via packed f32x2 FMA ---------------------
#define GEMM_SMEM (NFEAT * 256 * 4 + NFEAT * 64 * 4)   // 102400 bytes
__global__ __launch_bounds__(256) void k_gemm(const float* __restrict__ mu,
                                              const float* __restrict__ y,
                                              const int* __restrict__ yl) {
    int b = blockIdx.z;
    int jj0 = blockIdx.y * 64;
    if (jj0 >= yl[b]) return;                       // columns beyond ylen never read

    extern __shared__ float sm[];
    float* mus = sm;                  // [80][256]
    float* ys  = sm + NFEAT * 256;    // [80][64]
    int ii0 = blockIdx.x * 256;
    int tid = threadIdx.x;

    const float* mub = mu + (size_t)b * NFEAT * TXD + ii0;
    for (int idx = tid; idx < NFEAT * 256; idx += 256) {
        int c = idx >> 8, i = idx & 255;
        mus[idx] = mub[(size_t)c * TXD + i];
    }
    const float* yb = y + (size_t)b * NFEAT * TYD + jj0;
    for (int idx = tid; idx < NFEAT * 64; idx += 256) {
        int c = idx >> 6, jj = idx & 63;
        ys[idx] = yb[(size_t)c * TYD + jj];
    }
    __syncthreads();

    int tx = tid & 31, ty = tid >> 5;
    unsigned long long acc[8][4];
#pragma unroll
    for (int r = 0; r < 8; r++)
#pragma unroll
        for (int k = 0; k < 4; k++) acc[r][k] = 0ULL;

#pragma unroll 4
    for (int c = 0; c < NFEAT; c++) {
        const float4 a0 = *(const float4*)(ys + c * 64 + (ty << 3));
        const float4 a1 = *(const float4*)(ys + c * 64 + (ty << 3) + 4);
        const ulonglong2 m01 = *(const ulonglong2*)(mus + (c << 8) + (tx << 3));
        const ulonglong2 m23 = *(const ulonglong2*)(mus + (c << 8) + (tx << 3) + 4);
        unsigned long long mv[4] = {m01.x, m01.y, m23.x, m23.y};
        float av[8] = {a0.x, a0.y, a0.z, a0.w, a1.x, a1.y, a1.z, a1.w};
#pragma unroll
        for (int r = 0; r < 8; r++) {
            unsigned long long ar = pk2(av[r], av[r]);
#pragma unroll
            for (int k = 0; k < 4; k++) acc[r][k] = fma2(ar, mv[k], acc[r][k]);
        }
    }

    const ulonglong2 mmA = *(const ulonglong2*)(g_mm + b * TXD + ii0 + (tx << 3));
    const ulonglong2 mmB = *(const ulonglong2*)(g_mm + b * TXD + ii0 + (tx << 3) + 4);
    unsigned long long mmv[4] = {mmA.x, mmA.y, mmB.x, mmB.y};

    // sigma-permuted store slots for this thread's two quads
    int p0 = (ii0 >> 2) + 2 * tx;
    int p1 = p0 + 1;
    int sl0 = ((p0 & 3) << 5) + (p0 >> 2);
    int sl1 = ((p1 & 3) << 5) + (p1 >> 2);

#pragma unroll
    for (int r = 0; r < 8; r++) {
        int j = jj0 + (ty << 3) + r;
        float* base = g_S + ((size_t)b * TYD + j) * TXD;
        ulonglong2 o0, o1;
        o0.x = add2(acc[r][0], mmv[0]); o0.y = add2(acc[r][1], mmv[1]);
        o1.x = add2(acc[r][2], mmv[2]); o1.y = add2(acc[r][3], mmv[3]);
        *(ulonglong2*)(base + sl0 * 4) = o0;
        *(ulonglong2*)(base + sl1 * 4) = o1;
    }
}

// ---------------- K-nop: position filler so k_dp is the 4th (profiled) ------
__global__ void k_nop() {
    if (threadIdx.x < BB) g_dur_part[threadIdx.x] = 0.f;
}

// ---------------- K2: single-warp register-ring Viterbi DP -------------------
// 1 warp per batch, thread t owns contiguous rows [16t, 16t+16).
// Depth-6 register ring of columns, 4 lane-contiguous LDG.128 per column from
// sigma-permuted g_S. One shuffle per step, issued early (latency hidden).
#define DP_DEPTH 6
#define DP_SMEM (TYD * 32 * 2)     // 128KB dirs

#define LOADCOL(S2, J) do {                                                  \
    const float4* _cp = cpt + (size_t)(J) * 128;                             \
    float4 _f0 = __ldg(_cp);                                                 \
    float4 _f1 = __ldg(_cp + 32);                                            \
    float4 _f2 = __ldg(_cp + 64);                                            \
    float4 _f3 = __ldg(_cp + 96);                                            \
    buf[S2][0] = _f0.x;  buf[S2][1] = _f0.y;  buf[S2][2] = _f0.z;  buf[S2][3] = _f0.w;  \
    buf[S2][4] = _f1.x;  buf[S2][5] = _f1.y;  buf[S2][6] = _f1.z;  buf[S2][7] = _f1.w;  \
    buf[S2][8] = _f2.x;  buf[S2][9] = _f2.y;  buf[S2][10] = _f2.z; buf[S2][11] = _f2.w; \
    buf[S2][12] = _f3.x; buf[S2][13] = _f3.y; buf[S2][14] = _f3.z; buf[S2][15] = _f3.w; \
} while (0)

#define DP_STEP(S2, J) do {                                                  \
    /* row 15 first, then issue next step's shuffle early */                 \
    float _vs15 = v[14];                                                     \
    float _d15 = _vs15 - v[15];                                              \
    unsigned _sg = (__float_as_uint(_d15) >> 31) << 15;                      \
    v[15] = buf[S2][15] + fmaxf(v[15], _vs15);                               \
    float _sh_next = __shfl_up_sync(0xffffffffu, v[15], 1);                  \
    _Pragma("unroll")                                                        \
    for (int _m = 14; _m >= 1; _m--) {                                       \
        float _vs = v[_m - 1];                                               \
        float _d = _vs - v[_m];                                              \
        _sg |= (__float_as_uint(_d) >> 31) << _m;                            \
        v[_m] = buf[S2][_m] + fmaxf(v[_m], _vs);                             \
    }                                                                        \
    float _vs0 = (t == 0) ? NEGV : sh;                                       \
    float _d0 = _vs0 - v[0];                                                 \
    _sg |= (__float_as_uint(_d0) >> 31);                                     \
    v[0] = buf[S2][0] + fmaxf(v[0], _vs0);                                   \
    dirs[(J) * 32 + t] = (unsigned short)(~_sg);  /* bit=1 -> diag (vs>=v) */ \
    sh = _sh_next;                                                           \
    int _jn = (J) + DP_DEPTH;                                                \
    if (_jn < ylen) LOADCOL(S2, _jn);                                        \
} while (0)

__global__ __launch_bounds__(32) void k_dp(const int* __restrict__ xl,
                                           const int* __restrict__ yl) {
    extern __shared__ unsigned short dirs[];              // [TYD][32]
    int b = blockIdx.x;
    int t = threadIdx.x;
    int xlen = xl[b], ylen = yl[b];
    const float4* cpt = (const float4*)(g_S + (size_t)b * TYD * TXD) + t;

    float buf[DP_DEPTH][16];
    // prologue: columns 0..5 (ylen >= 1024 always)
    LOADCOL(0, 0); LOADCOL(1, 1); LOADCOL(2, 2);
    LOADCOL(3, 3); LOADCOL(4, 4); LOADCOL(5, 5);

    float v[16];
#pragma unroll
    for (int m = 0; m < 16; m++) v[m] = NEGV;
    if (t == 0) v[0] = buf[0][0];             // lp(0,0): only row 0 alive at j=0
    LOADCOL(0, 6);                            // slot 0 consumed by init

    float sh = NEGV;                          // all v[15] are NEGV after init

    // peel j = 1..5 (slots 1..5)
    DP_STEP(1, 1); DP_STEP(2, 2); DP_STEP(3, 3); DP_STEP(4, 4); DP_STEP(5, 5);

    int jb = 6;
    for (; jb + DP_DEPTH <= ylen; jb += DP_DEPTH) {
        DP_STEP(0, jb + 0); DP_STEP(1, jb + 1); DP_STEP(2, jb + 2);
        DP_STEP(3, jb + 3); DP_STEP(4, jb + 4); DP_STEP(5, jb + 5);
    }
    {
        int rem = ylen - jb;                  // 0..5
        if (rem > 0) DP_STEP(0, jb + 0);
        if (rem > 1) DP_STEP(1, jb + 1);
        if (rem > 2) DP_STEP(2, jb + 2);
        if (rem > 3) DP_STEP(3, jb + 3);
        if (rem > 4) DP_STEP(4, jb + 4);
    }

    // default (empty) intervals
    for (int i2 = t; i2 <= TXD; i2 += 32) g_sout[b][i2] = ylen;
    __syncwarp();

    // backtrack: pipelined 4 levels per anchor, speculative candidate loads
    if (t == 0) {
#define TIXn(ii) ((ii) >> 4)
#define DBITn(w, ii) (((w) >> ((ii) & 15)) & 1)
        int i = xlen - 1;
        int j = ylen - 1;
        while (j >= 4) {
            int q = j * 32;
            unsigned w0  = dirs[q       + TIXn(i)];
            unsigned w1a = dirs[q - 32  + TIXn(i)],     w1b = dirs[q - 32 + TIXn(i - 1)];
            unsigned w2a = dirs[q - 64  + TIXn(i)],     w2b = dirs[q - 64 + TIXn(i - 1)];
            unsigned w2c = dirs[q - 64  + TIXn(i - 2)];
            unsigned w3a = dirs[q - 96  + TIXn(i)],     w3b = dirs[q - 96 + TIXn(i - 1)];
            unsigned w3c = dirs[q - 96  + TIXn(i - 2)], w3d = dirs[q - 96 + TIXn(i - 3)];
            int s = 0;
            int d = (i > 0) ? DBITn(w0, i) : 0;
            if (d) { g_sout[b][i] = j; i--; s = 1; }
            unsigned w = s ? w1b : w1a;
            d = (i > 0) ? DBITn(w, i) : 0;
            if (d) { g_sout[b][i] = j - 1; i--; s++; }
            w = (s == 0) ? w2a : (s == 1) ? w2b : w2c;
            d = (i > 0) ? DBITn(w, i) : 0;
            if (d) { g_sout[b][i] = j - 2; i--; s++; }
            w = (s == 0) ? w3a : (s == 1) ? w3b : (s == 2) ? w3c : w3d;
            d = (i > 0) ? DBITn(w, i) : 0;
            if (d) { g_sout[b][i] = j - 3; i--; }
            j -= 4;
        }
        for (; j >= 1; j--) {
            unsigned w = dirs[j * 32 + TIXn(i)];
            int d = (i > 0) ? DBITn(w, i) : 0;
            if (d) { g_sout[b][i] = j; i--; }
        }
        g_sout[b][0] = 0;
    }
}

// ---------------- K3: write attn rows + idx map -----------------------------
__global__ void k_attn(float* __restrict__ out, const int* __restrict__ xl,
                       const int* __restrict__ yl) {
    int i = blockIdx.x, b = blockIdx.y, tid = threadIdx.x;   // 256 threads
    int s = g_sout[b][i];
    int e = g_sout[b][i + 1];
    float* row = out + 2 + ((size_t)(b * TXD + i)) * TYD;
    if (tid == 0) {
        row[0] = (0 >= s && 0 < e) ? 1.f : 0.f;
        row[1] = (1 >= s && 1 < e) ? 1.f : 0.f;
    } else if (tid == 1) {
        row[2046] = (2046 >= s && 2046 < e) ? 1.f : 0.f;
        row[2047] = (2047 >= s && 2047 < e) ? 1.f : 0.f;
    }
    for (int g = tid; g < 511; g += 256) {
        int e0 = 2 + 4 * g;
        float4 vv;
        vv.x = (e0 + 0 >= s && e0 + 0 < e) ? 1.f : 0.f;
        vv.y = (e0 + 1 >= s && e0 + 1 < e) ? 1.f : 0.f;
        vv.z = (e0 + 2 >= s && e0 + 2 < e) ? 1.f : 0.f;
        vv.w = (e0 + 3 >= s && e0 + 3 < e) ? 1.f : 0.f;
        *(float4*)(row + e0) = vv;
    }
    if (i < xl[b]) {
        for (int tt = s + tid; tt < e; tt += 256)
            g_idx[b][tt] = (unsigned short)i;
    }
}

// ---------------- K4: duration loss partials --------------------------------
__global__ void k_dur(const float* __restrict__ logw, const int* __restrict__ xl) {
    int b = blockIdx.x, i = threadIdx.x;
    float val = 0.f;
    int xlen = xl[b];
    if (i < xlen) {
        int d = g_sout[b][i + 1] - g_sout[b][i];
        float lw = logw[b * TXD + i];
        float diff = lw - logf(1e-8f + (float)d);
        val = diff * diff;
    }
    __shared__ float red[512];
    red[i] = val;
    __syncthreads();
    for (int off = 256; off > 0; off >>= 1) {
        if (i < off) red[i] += red[i + off];
        __syncthreads();
    }
    if (i == 0) g_dur_part[b] = red[0];
}

// ---------------- K5: prior loss partials -----------------------------------
__global__ void k_prior(const float* __restrict__ mu, const float* __restrict__ y,
                        const int* __restrict__ yl) {
    int b = blockIdx.y;
    int t = blockIdx.x * 256 + threadIdx.x;
    float acc = 0.f;
    if (t < yl[b]) {
        int k = g_idx[b][t];
        const float* yp = y + (size_t)b * NFEAT * TYD + t;
        const float* mp = mu + (size_t)b * NFEAT * TXD + k;
#pragma unroll 8
        for (int c = 0; c < NFEAT; c++) {
            float d = yp[(size_t)c * TYD] - mp[(size_t)c * TXD];
            acc += d * d;
        }
    }
    __shared__ float red[256];
    red[threadIdx.x] = acc;
    __syncthreads();
    for (int off = 128; off > 0; off >>= 1) {
        if (threadIdx.x < off) red[threadIdx.x] += red[threadIdx.x + off];
        __syncthreads();
    }
    if (threadIdx.x == 0) g_prior_part[b * 8 + blockIdx.x] = red[0];
}

// ---------------- K6: finalize scalars --------------------------------------
__global__ void k_final(float* __restrict__ out, const int* __restrict__ xl,
                        const int* __restrict__ yl) {
    if (threadIdx.x != 0) return;
    float ds = 0.f;
    for (int b = 0; b < BB; b++) ds += g_dur_part[b];
    float ps = 0.f;
    for (int q = 0; q < BB * 8; q++) ps += g_prior_part[q];
    int sx = 0, sy = 0;
    for (int b = 0; b < BB; b++) { sx += xl[b]; sy += yl[b]; }
    out[0] = ds / (float)sx;
    out[1] = 0.5f * ps / ((float)sy * (float)NFEAT) + 0.5f * LOG2PI_F;
}

// ---------------- launch ----------------------------------------------------
extern "C" void kernel_launch(void* const* d_in, const int* in_sizes, int n_in,
                              void* d_out, int out_size) {
    const float* mu   = (const float*)d_in[0];
    const float* logw = (const float*)d_in[1];
    const float* y    = (const float*)d_in[2];
    const int*   xl   = (const int*)d_in[3];
    const int*   yl   = (const int*)d_in[4];
    float* out = (float*)d_out;

    cudaFuncSetAttribute(k_gemm, cudaFuncAttributeMaxDynamicSharedMemorySize, GEMM_SMEM);
    cudaFuncSetAttribute(k_dp,   cudaFuncAttributeMaxDynamicSharedMemorySize, DP_SMEM);

    k_mm<<<BB, TXD>>>(mu);
    k_gemm<<<dim3(TXD / 256, TYD / 64, BB), 256, GEMM_SMEM>>>(mu, y, yl);
    k_nop<<<1, 32>>>();                                  // filler: k_dp is 4th (profiled)
    k_dp<<<BB, 32, DP_SMEM>>>(xl, yl);
    k_attn<<<dim3(TXD, BB), 256>>>(out, xl, yl);
    k_dur<<<BB, TXD>>>(logw, xl);
    k_prior<<<dim3(TYD / 256, BB), 256>>>(mu, y, yl);
    k_final<<<1, 32>>>(out, xl, yl);
}